// round 1
// baseline (speedup 1.0000x reference)
#include <cuda_runtime.h>
#include <math.h>

#define Pp 8
#define Kk 9
#define RCn 8
#define FCn 768
#define Bb 8
#define HW 4096

// ---------------- scratch (device globals; no allocation) ----------------
__device__ float g_kern[Pp*81];
__device__ float g_c1[Bb*RCn*HW];
__device__ float g_carrier[Bb*RCn*HW];
__device__ float g_cmean[Bb*HW];
__device__ float g_densraw[Bb*HW];
__device__ float g_hp[Bb*HW];
__device__ float g_asup[Bb*HW];
__device__ float g_stats[Bb*5];   // mnA,mxA,mnD,mxD,meanD
__device__ float g_ss1[Bb*HW];
__device__ float g_gate0[Bb*HW];
__device__ float g_mask0[Bb*HW];
__device__ float g_eroded[Bb*HW];
__device__ float g_ssf[Bb*HW];

__device__ __forceinline__ float geluf(float x){ return 0.5f*x*(1.0f+erff(x*0.70710678118654752f)); }
__device__ __forceinline__ float sigmf(float x){ return 1.0f/(1.0f+expf(-x)); }

// ---------------- kernel bank (deterministic, from proto_delta) ----------------
__global__ void k_bank(const float* __restrict__ pd){
    int i = blockIdx.x;          // prototype
    int t = threadIdx.x;         // 128 threads, 81 active
    __shared__ float red[128];
    float ridge = 0.f;
    if (t < 81){
        int r = t/9, c = t%9;
        float y = -1.0f + 0.25f*(float)r;
        float x = -1.0f + 0.25f*(float)c;
        double angd = 6.283185307179586476925286766559 * (double)i / 8.0;
        const float Ls[3] = {0.45f,0.75f,1.05f};
        const float Ws[3] = {0.14f,0.2f,0.28f};
        float L = Ls[i%3], Wd = Ws[(i/3)%3];
        float ca = (float)cos(angd), sa = (float)sin(angd);
        float xr =  x*ca + y*sa;
        float yr = -x*sa + y*ca;
        float tpr = 1.0f - fminf(fabsf(xr)/L, 1.0f);
        tpr = tpr*sqrtf(tpr);                       // ^1.5
        float ax = xr/L, ay = yr/Wd;
        float core = expf(-0.5f*(ax*ax + ay*ay));
        float lobe = fmaxf(1.0f - ay*ay, 0.0f);
        ridge = tpr*core*lobe;
    }
    red[t] = (t<81)? ridge : 0.f;
    __syncthreads();
    for(int s=64;s>0;s>>=1){ if(t<s) red[t]+=red[t+s]; __syncthreads(); }
    float mean = red[0]/81.0f;
    __syncthreads();
    float kv = (t<81)? (ridge-mean) : 0.f;
    red[t] = fabsf(kv);
    __syncthreads();
    for(int s=64;s>0;s>>=1){ if(t<s) red[t]+=red[t+s]; __syncthreads(); }
    float nrm = fmaxf(red[0], 1e-6f);
    if (t<81) g_kern[i*81+t] = kv/nrm + 0.05f*pd[i*81+t];
}

// ---------------- 1x1 conv 768->8 + gelu ----------------
__global__ void k_conv1(const float* __restrict__ fm,
                        const float* __restrict__ w,
                        const float* __restrict__ bias){
    __shared__ float sw[FCn*RCn];     // [c][o], 24KB
    int tid = threadIdx.x;            // 128
    for(int idx = tid; idx < FCn*RCn; idx += 128){
        int o = idx / FCn, c = idx % FCn;
        sw[c*RCn + o] = w[idx];
    }
    __syncthreads();
    int g = blockIdx.x*128 + tid;
    int b = g >> 12, pix = g & 4095;
    const float* xp = fm + (size_t)b*FCn*HW + pix;
    float acc[RCn];
    #pragma unroll
    for(int o=0;o<RCn;o++) acc[o]=bias[o];
    #pragma unroll 8
    for(int c=0;c<FCn;c++){
        float xv = __ldg(xp + (size_t)c*HW);
        const float* wr = &sw[c*RCn];
        #pragma unroll
        for(int o=0;o<RCn;o++) acc[o] = fmaf(xv, wr[o], acc[o]);
    }
    float* op = g_c1 + (b*RCn<<12) + pix;
    #pragma unroll
    for(int o=0;o<RCn;o++) op[o<<12] = geluf(acc[o]);
}

// ---------------- 3x3 conv 8->8 + gelu, + channel mean / |.|-mean ----------------
__global__ void k_conv3(const float* __restrict__ w, const float* __restrict__ bias){
    __shared__ float s_in[RCn][18][18];
    __shared__ float s_w[RCn*RCn*9];
    __shared__ float s_b[RCn];
    int tid = threadIdx.x;              // 256
    int blk = blockIdx.x;               // 128 = 8 * 16 tiles
    int b = blk >> 4;
    int t4 = blk & 15, ty = t4 >> 2, tx = t4 & 3;
    for(int idx=tid; idx<RCn*RCn*9; idx+=256) s_w[idx]=w[idx];
    if (tid < RCn) s_b[tid]=bias[tid];
    for(int idx=tid; idx<RCn*324; idx+=256){
        int ch = idx/324, rem = idx%324;
        int r = rem/18, c = rem%18;
        int gy = ty*16 + r - 1, gx = tx*16 + c - 1;
        float v = 0.f;
        if (gy>=0 && gy<64 && gx>=0 && gx<64)
            v = g_c1[((b*RCn+ch)<<12) + (gy<<6) + gx];
        s_in[ch][r][c] = v;
    }
    __syncthreads();
    int ly = tid >> 4, lx = tid & 15;
    float sum=0.f, asum=0.f;
    float outv[RCn];
    #pragma unroll
    for(int o=0;o<RCn;o++){
        float acc = s_b[o];
        #pragma unroll
        for(int i=0;i<RCn;i++){
            const float* wr = &s_w[(o*RCn+i)*9];
            #pragma unroll
            for(int dy=0;dy<3;dy++)
                #pragma unroll
                for(int dx=0;dx<3;dx++)
                    acc = fmaf(wr[dy*3+dx], s_in[i][ly+dy][lx+dx], acc);
        }
        float gv = geluf(acc);
        outv[o]=gv; sum+=gv; asum+=fabsf(gv);
    }
    int pix = ((ty*16+ly)<<6) + tx*16+lx;
    #pragma unroll
    for(int o=0;o<RCn;o++) g_carrier[((b*RCn+o)<<12)+pix] = outv[o];
    g_cmean  [(b<<12)+pix] = sum*0.125f;
    g_densraw[(b<<12)+pix] = asum*0.125f;
}

// ---------------- hp = mean - avg3(mean); asup = avg3(|hp|); per-image stats -----
__global__ void k_hpstats(){
    int b = blockIdx.x;
    int tid = threadIdx.x;              // 1024
    __shared__ float s_cm[HW];
    __shared__ float s_hp[HW];
    __shared__ float r0[32],r1[32],r2[32],r3[32],r4[32];
    for(int i=tid;i<HW;i+=1024) s_cm[i]=g_cmean[(b<<12)+i];
    __syncthreads();
    float lmnA=1e30f,lmxA=-1e30f,lmnD=1e30f,lmxD=-1e30f,lsD=0.f;
    for(int i=tid;i<HW;i+=1024){
        int y=i>>6, x=i&63;
        float s=0.f;
        for(int dy=-1;dy<=1;dy++){ int yy=y+dy; if((unsigned)yy>63u) continue;
            for(int dx=-1;dx<=1;dx++){ int xx=x+dx; if((unsigned)xx>63u) continue;
                s += s_cm[(yy<<6)+xx]; } }
        float hp = s_cm[i] - s/9.0f;
        s_hp[i]=hp;
        g_hp[(b<<12)+i]=hp;
        float d = g_densraw[(b<<12)+i];
        lmnD=fminf(lmnD,d); lmxD=fmaxf(lmxD,d); lsD+=d;
    }
    __syncthreads();
    for(int i=tid;i<HW;i+=1024){
        int y=i>>6, x=i&63;
        float s=0.f;
        for(int dy=-1;dy<=1;dy++){ int yy=y+dy; if((unsigned)yy>63u) continue;
            for(int dx=-1;dx<=1;dx++){ int xx=x+dx; if((unsigned)xx>63u) continue;
                s += fabsf(s_hp[(yy<<6)+xx]); } }
        float a = s/9.0f;
        g_asup[(b<<12)+i]=a;
        lmnA=fminf(lmnA,a); lmxA=fmaxf(lmxA,a);
    }
    // block reduce 5 values
    for(int off=16;off;off>>=1){
        lmnA=fminf(lmnA,__shfl_down_sync(0xffffffffu,lmnA,off));
        lmxA=fmaxf(lmxA,__shfl_down_sync(0xffffffffu,lmxA,off));
        lmnD=fminf(lmnD,__shfl_down_sync(0xffffffffu,lmnD,off));
        lmxD=fmaxf(lmxD,__shfl_down_sync(0xffffffffu,lmxD,off));
        lsD +=      __shfl_down_sync(0xffffffffu,lsD ,off);
    }
    int wid=tid>>5, lane=tid&31;
    if(lane==0){ r0[wid]=lmnA; r1[wid]=lmxA; r2[wid]=lmnD; r3[wid]=lmxD; r4[wid]=lsD; }
    __syncthreads();
    if(tid<32){
        float a0=r0[tid],a1=r1[tid],a2=r2[tid],a3=r3[tid],a4=r4[tid];
        for(int off=16;off;off>>=1){
            a0=fminf(a0,__shfl_down_sync(0xffffffffu,a0,off));
            a1=fmaxf(a1,__shfl_down_sync(0xffffffffu,a1,off));
            a2=fminf(a2,__shfl_down_sync(0xffffffffu,a2,off));
            a3=fmaxf(a3,__shfl_down_sync(0xffffffffu,a3,off));
            a4+=     __shfl_down_sync(0xffffffffu,a4,off);
        }
        if(tid==0){
            g_stats[b*5+0]=a0; g_stats[b*5+1]=a1;
            g_stats[b*5+2]=a2; g_stats[b*5+3]=a3;
            g_stats[b*5+4]=a4/(float)HW;
        }
    }
}

// ---------------- responses (9x9 bank conv) + softmax top-2 + support gates ----
__global__ void k_resp(const float* __restrict__ theta, const float* __restrict__ length,
                       const float* __restrict__ width, const float* __restrict__ plog){
    __shared__ float s_hp[24*24];
    __shared__ float s_k[Pp*81];
    int tid=threadIdx.x;                // 256
    int blk=blockIdx.x;                 // 128
    int b = blk>>4, t4 = blk&15, ty = t4>>2, tx = t4&3;
    for(int i=tid;i<Pp*81;i+=256) s_k[i]=g_kern[i];
    for(int i=tid;i<576;i+=256){
        int r=i/24,c=i%24;
        int gy=ty*16+r-4, gx=tx*16+c-4;
        float v=0.f;
        if((unsigned)gy<64u && (unsigned)gx<64u) v=g_hp[(b<<12)+(gy<<6)+gx];
        s_hp[i]=v;
    }
    __syncthreads();
    int ly=tid>>4, lx=tid&15;
    float resp[Pp];
    #pragma unroll
    for(int p=0;p<Pp;p++) resp[p]=0.f;
    #pragma unroll
    for(int dy=0;dy<9;dy++){
        #pragma unroll
        for(int dx=0;dx<9;dx++){
            float hv = s_hp[(ly+dy)*24 + lx+dx];
            int off = dy*9+dx;
            #pragma unroll
            for(int p=0;p<Pp;p++) resp[p]=fmaf(s_k[p*81+off],hv,resp[p]);
        }
    }
    int gi = (b<<12) + ((ty*16+ly)<<6) + tx*16+lx;
    float th = tanhf(theta[gi])*3.14159265358979f;
    float lv = sigmf(length[gi])*0.85f + 0.25f;
    float wv = sigmf(width[gi]) *0.22f + 0.08f;
    const float ORI[8]={0.0f,0.78539816f,1.57079633f,2.35619449f,
                        3.14159265f,3.92699082f,4.71238898f,5.49778714f};
    const float LA[8]={0.45f,0.75f,1.05f,0.45f,0.75f,1.05f,0.45f,0.75f};
    const float WA[8]={0.14f,0.14f,0.14f,0.2f,0.2f,0.2f,0.28f,0.28f};
    float bias[8];
    #pragma unroll
    for(int p=0;p<8;p++){
        float ts = cosf(th - ORI[p]);
        float dl = lv - LA[p];
        float dw = wv - WA[p];
        bias[p] = plog[((b*8+p)<<12) + (gi&4095)] + 1.25f*ts - (dl*dl)/0.08f - (dw*dw)/0.01f;
    }
    int i1=0; float b1=bias[0];
    #pragma unroll
    for(int p=1;p<8;p++) if(bias[p]>b1){b1=bias[p];i1=p;}
    int i2=-1; float b2=-1e30f;
    #pragma unroll
    for(int p=0;p<8;p++){ if(p==i1) continue; if(bias[p]>b2){b2=bias[p];i2=p;} }
    float e = expf(b2-b1);
    float w1 = 1.0f/(1.0f+e);
    float w2 = e/(1.0f+e);
    float ss=0.f;
    #pragma unroll
    for(int p=0;p<8;p++){
        float wp = (p==i1)?w1:((p==i2)?w2:0.f);
        ss = fmaf(wp, resp[p], ss);
    }
    g_ss1[gi]=ss;
    // support evidence
    float mnA=g_stats[b*5+0], mxA=g_stats[b*5+1];
    float mnD=g_stats[b*5+2], mxD=g_stats[b*5+3], meanD=g_stats[b*5+4];
    float csup = (g_asup[gi]-mnA)/fmaxf(mxA-mnA,1e-6f);
    float mC = fmaxf(meanD,1e-6f);
    float d = g_densraw[gi]/mC;
    float dmn = mnD/mC, dmx = mxD/mC;
    float dsup = (d-dmn)/fmaxf(dmx-dmn,1e-6f);
    float ev = 0.65f*csup + 0.35f*dsup;
    g_gate0[gi] = sigmf((ev-0.2f)/0.08f);
    g_mask0[gi] = (ev>=0.2f)?1.0f:0.0f;
}

// ---------------- 5x5 erosion of mask0 ----------------
__global__ void k_erode(){
    __shared__ float s[20*20];
    int tid=threadIdx.x;
    int blk=blockIdx.x;
    int b = blk>>4, t4 = blk&15, ty = t4>>2, tx = t4&3;
    for(int i=tid;i<400;i+=256){
        int r=i/20,c=i%20;
        int gy=ty*16+r-2, gx=tx*16+c-2;
        float v=1.0f;  // identity for min over valid window
        if((unsigned)gy<64u && (unsigned)gx<64u) v=g_mask0[(b<<12)+(gy<<6)+gx];
        s[i]=v;
    }
    __syncthreads();
    int ly=tid>>4, lx=tid&15;
    float m=1.0f;
    #pragma unroll
    for(int dy=0;dy<5;dy++)
        #pragma unroll
        for(int dx=0;dx<5;dx++)
            m=fminf(m, s[(ly+dy)*20 + lx+dx]);
    g_eroded[(b<<12) + ((ty*16+ly)<<6) + tx*16+lx] = m;
}

// ---------------- morphology close-out + blob + stroke gating -> ss_final ------
__global__ void k_gate(const float* __restrict__ objn, const float* __restrict__ alpha,
                       const float* __restrict__ curv){
    __shared__ float s_er[24*24];   // halo 4 (two stacked 5x5 dilations = 9x9 max)
    __shared__ float s_g0[20*20];   // halo 2
    __shared__ float s_ss[18*18];   // halo 1 (zero pad == reference avg3)
    __shared__ float s_ob[18*18];   // sigmoid(objectness), halo 1
    int tid=threadIdx.x;
    int blk=blockIdx.x;
    int b = blk>>4, t4 = blk&15, ty = t4>>2, tx = t4&3;
    for(int i=tid;i<576;i+=256){
        int r=i/24,c=i%24;
        int gy=ty*16+r-4, gx=tx*16+c-4;
        float v=0.f;
        if((unsigned)gy<64u && (unsigned)gx<64u) v=g_eroded[(b<<12)+(gy<<6)+gx];
        s_er[i]=v;
    }
    for(int i=tid;i<400;i+=256){
        int r=i/20,c=i%20;
        int gy=ty*16+r-2, gx=tx*16+c-2;
        float v=0.f;
        if((unsigned)gy<64u && (unsigned)gx<64u) v=g_gate0[(b<<12)+(gy<<6)+gx];
        s_g0[i]=v;
    }
    for(int i=tid;i<324;i+=256){
        int r=i/18,c=i%18;
        int gy=ty*16+r-1, gx=tx*16+c-1;
        float vs=0.f, vo=0.f;
        if((unsigned)gy<64u && (unsigned)gx<64u){
            int gg=(b<<12)+(gy<<6)+gx;
            vs=g_ss1[gg];
            vo=sigmf(objn[gg]);
        }
        s_ss[i]=vs; s_ob[i]=vo;
    }
    __syncthreads();
    int ly=tid>>4, lx=tid&15;
    float m9=0.f;
    #pragma unroll
    for(int dy=0;dy<9;dy++)
        #pragma unroll
        for(int dx=0;dx<9;dx++)
            m9=fmaxf(m9, s_er[(ly+dy)*24 + lx+dx]);
    float g5=0.f;
    #pragma unroll
    for(int dy=0;dy<5;dy++)
        #pragma unroll
        for(int dx=0;dx<5;dx++)
            g5=fmaxf(g5, s_g0[(ly+dy)*20 + lx+dx]);
    float gate = g5*m9;
    float so=0.f, sv=0.f;
    #pragma unroll
    for(int dy=0;dy<3;dy++)
        #pragma unroll
        for(int dx=0;dx<3;dx++){
            so += s_ob[(ly+dy)*18 + lx+dx];
            sv += s_ss[(ly+dy)*18 + lx+dx];
        }
    float blob = (so/9.0f)*gate;
    float ss2 = s_ss[(ly+1)*18 + lx+1] - sv/9.0f;
    int gi = (b<<12) + ((ty*16+ly)<<6) + tx*16+lx;
    float meanD = g_stats[b*5+4];
    float d = g_densraw[gi]/fmaxf(meanD,1e-6f);
    float sg = sigmf(alpha[gi])*blob*(0.7f + 0.3f*fminf(fmaxf(d,0.f),2.0f));
    g_ssf[gi] = sg*ss2*(1.0f + 0.15f*tanhf(curv[gi]));
}

// ---------------- feats -> pm1+gelu -> pm2 -> out ----------------
__global__ void k_out(const float* __restrict__ theta, const float* __restrict__ curv,
                      const float* __restrict__ pm1w, const float* __restrict__ pm1b,
                      const float* __restrict__ pm2w, const float* __restrict__ pm2b,
                      float* __restrict__ out){
    __shared__ float s_p2[FCn*RCn];   // [o][k], 24KB
    __shared__ float s_b2[FCn];
    __shared__ float s_p1[RCn*12];
    __shared__ float s_b1[RCn];
    int tid = threadIdx.x;            // 256
    for(int i=tid;i<FCn*RCn;i+=256) s_p2[i]=pm2w[i];
    for(int i=tid;i<FCn;i+=256) s_b2[i]=pm2b[i];
    if(tid<RCn*12) s_p1[tid]=pm1w[tid];
    if(tid<RCn) s_b1[tid]=pm1b[tid];
    __syncthreads();
    int g = blockIdx.x*256 + tid;
    int b = g>>12, pix = g&4095;
    float ss = g_ssf[g];
    float th = tanhf(theta[g])*3.14159265358979f;
    float cv = tanhf(curv[g]);
    float f[12];
    #pragma unroll
    for(int o=0;o<RCn;o++) f[o] = g_carrier[((b*RCn+o)<<12)+pix]*ss;
    f[8]=ss; f[9]=cosf(th)*ss; f[10]=sinf(th)*ss; f[11]=cv*ss;
    float h[RCn];
    #pragma unroll
    for(int o=0;o<RCn;o++){
        float acc = s_b1[o];
        #pragma unroll
        for(int j=0;j<12;j++) acc = fmaf(s_p1[o*12+j], f[j], acc);
        h[o]=geluf(acc);
    }
    float* op = out + ((size_t)b*FCn<<12) + pix;
    #pragma unroll 4
    for(int o=0;o<FCn;o++){
        const float* wr = &s_p2[o*RCn];
        float acc = s_b2[o];
        #pragma unroll
        for(int k=0;k<RCn;k++) acc = fmaf(wr[k], h[k], acc);
        op[(size_t)o<<12] = acc;
    }
}

extern "C" void kernel_launch(void* const* d_in, const int* in_sizes, int n_in,
                              void* d_out, int out_size){
    const float* fm     = (const float*)d_in[0];
    const float* theta  = (const float*)d_in[1];
    const float* length = (const float*)d_in[2];
    const float* width  = (const float*)d_in[3];
    const float* curv   = (const float*)d_in[4];
    const float* alpha  = (const float*)d_in[5];
    const float* objn   = (const float*)d_in[6];
    const float* plog   = (const float*)d_in[7];
    const float* fp1w   = (const float*)d_in[8];
    const float* fp1b   = (const float*)d_in[9];
    const float* fp2w   = (const float*)d_in[10];
    const float* fp2b   = (const float*)d_in[11];
    const float* pm1w   = (const float*)d_in[12];
    const float* pm1b   = (const float*)d_in[13];
    const float* pm2w   = (const float*)d_in[14];
    const float* pm2b   = (const float*)d_in[15];
    const float* pd     = (const float*)d_in[16];
    float* out = (float*)d_out;

    k_bank   <<<Pp, 128>>>(pd);
    k_conv1  <<<256, 128>>>(fm, fp1w, fp1b);
    k_conv3  <<<128, 256>>>(fp2w, fp2b);
    k_hpstats<<<Bb, 1024>>>();
    k_resp   <<<128, 256>>>(theta, length, width, plog);
    k_erode  <<<128, 256>>>();
    k_gate   <<<128, 256>>>(objn, alpha, curv);
    k_out    <<<128, 256>>>(theta, curv, pm1w, pm1b, pm2w, pm2b, out);
}

// round 2
// speedup vs baseline: 1.1440x; 1.1440x over previous
#include <cuda_runtime.h>
#include <math.h>

#define Pp 8
#define RCn 8
#define FCn 768
#define Bb 8
#define HW 4096

// ---------------- scratch (device globals; no allocation) ----------------
__device__ float g_kern[Pp*81];
__device__ float g_c1[Bb*RCn*HW];
__device__ float g_carrier[Bb*RCn*HW];
__device__ float g_densraw[Bb*HW];
__device__ float g_hp[Bb*HW];
__device__ float g_asup[Bb*HW];
__device__ float g_part[Bb*16*5];   // per-tile partials: mnA,mxA,mnD,mxD,sumD
__device__ float g_ssf[Bb*HW];

__device__ __forceinline__ float geluf(float x){ return 0.5f*x*(1.0f+erff(x*0.70710678118654752f)); }
__device__ __forceinline__ float sigmf(float x){ return 1.0f/(1.0f+expf(-x)); }

// =====================================================================
// k_conv1: 1x1 conv 768->8 + gelu. 2-way channel split per block.
// Blocks 0..7 additionally build the filter bank (prototype = blockIdx).
// =====================================================================
__global__ void k_conv1(const float* __restrict__ fm,
                        const float* __restrict__ w,
                        const float* __restrict__ bias,
                        const float* __restrict__ pd){
    __shared__ float sw[FCn*RCn];       // [c][o] 24KB
    __shared__ float s_part[128*RCn];   // partial sums from half 1
    __shared__ float s_red[256];
    int tid = threadIdx.x;              // 256
    for(int idx = tid; idx < FCn*RCn; idx += 256){
        int o = idx / FCn, c = idx % FCn;
        sw[c*RCn + o] = w[idx];
    }
    __syncthreads();
    int lane = tid & 127;               // pixel lane
    int half = tid >> 7;                // channel half
    int g = blockIdx.x*128 + lane;      // global pixel (0..32767)
    int b = g >> 12, pix = g & 4095;
    const float* xp = fm + (size_t)b*FCn*HW + (size_t)(half*384)*HW + pix;
    float acc[RCn];
    #pragma unroll
    for(int o=0;o<RCn;o++) acc[o]=0.f;
    #pragma unroll 8
    for(int c=0;c<384;c++){
        float xv = __ldg(xp + (size_t)c*HW);
        const float* wr = &sw[(half*384 + c)*RCn];
        #pragma unroll
        for(int o=0;o<RCn;o++) acc[o] = fmaf(xv, wr[o], acc[o]);
    }
    if (half == 1){
        #pragma unroll
        for(int o=0;o<RCn;o++) s_part[lane*RCn+o] = acc[o];
    }
    __syncthreads();
    if (half == 0){
        float* op = g_c1 + (b*RCn<<12) + pix;
        #pragma unroll
        for(int o=0;o<RCn;o++)
            op[o<<12] = geluf(acc[o] + s_part[lane*RCn+o] + bias[o]);
    }
    // ---- filter bank (blocks 0..7) ----
    if (blockIdx.x < 8){
        int i = blockIdx.x;
        float ridge = 0.f;
        if (tid < 81){
            int r = tid/9, c = tid%9;
            float y = -1.0f + 0.25f*(float)r;
            float x = -1.0f + 0.25f*(float)c;
            double angd = 6.283185307179586476925286766559 * (double)i / 8.0;
            const float Ls[3] = {0.45f,0.75f,1.05f};
            const float Ws[3] = {0.14f,0.2f,0.28f};
            float L = Ls[i%3], Wd = Ws[(i/3)%3];
            float ca = (float)cos(angd), sa = (float)sin(angd);
            float xr =  x*ca + y*sa;
            float yr = -x*sa + y*ca;
            float tpr = 1.0f - fminf(fabsf(xr)/L, 1.0f);
            tpr = tpr*sqrtf(tpr);
            float ax = xr/L, ay = yr/Wd;
            float core = expf(-0.5f*(ax*ax + ay*ay));
            float lobe = fmaxf(1.0f - ay*ay, 0.0f);
            ridge = tpr*core*lobe;
        }
        __syncthreads();
        s_red[tid] = (tid<81)? ridge : 0.f;
        __syncthreads();
        for(int s=128;s>0;s>>=1){ if(tid<s) s_red[tid]+=s_red[tid+s]; __syncthreads(); }
        float mean = s_red[0]/81.0f;
        __syncthreads();
        float kv = (tid<81)? (ridge-mean) : 0.f;
        s_red[tid] = fabsf(kv);
        __syncthreads();
        for(int s=128;s>0;s>>=1){ if(tid<s) s_red[tid]+=s_red[tid+s]; __syncthreads(); }
        float nrm = fmaxf(s_red[0], 1e-6f);
        if (tid<81) g_kern[i*81+tid] = kv/nrm + 0.05f*pd[i*81+tid];
    }
}

// =====================================================================
// k_conv3hp: 3x3 conv 8->8 + gelu over 20x20 halo region per 16x16 tile,
// carrier (interior store), cmean, hp, asup, densraw + per-tile stat partials.
// =====================================================================
__global__ void k_conv3hp(const float* __restrict__ w, const float* __restrict__ bias){
    __shared__ float s_in[RCn*22*22];   // 15.1KB, halo 3
    __shared__ float s_w[RCn*RCn*9];
    __shared__ float s_b[RCn];
    __shared__ float s_cm[20*20];
    __shared__ float s_dr[20*20];
    __shared__ float s_hp[18*18];
    __shared__ float s_red[256];
    int tid = threadIdx.x;              // 256
    int blk = blockIdx.x;               // 128 = 8 images * 16 tiles
    int b = blk >> 4;
    int t4 = blk & 15, ty = t4 >> 2, tx = t4 & 3;
    for(int idx=tid; idx<RCn*RCn*9; idx+=256) s_w[idx]=w[idx];
    if (tid < RCn) s_b[tid]=bias[tid];
    for(int idx=tid; idx<RCn*484; idx+=256){
        int ch = idx/484, rem = idx%484;
        int r = rem/22, c = rem%22;
        int gy = ty*16 + r - 3, gx = tx*16 + c - 3;
        float v = 0.f;
        if ((unsigned)gy<64u && (unsigned)gx<64u)
            v = g_c1[((b*RCn+ch)<<12) + (gy<<6) + gx];
        s_in[ch*484 + r*22 + c] = v;
    }
    __syncthreads();
    // conv3+gelu over 20x20 (image coords ty*16-2 .. +17)
    for(int i=tid; i<400; i+=256){
        int oy=i/20, ox=i%20;
        int gy=ty*16+oy-2, gx=tx*16+ox-2;
        float sum=0.f, asum=0.f;
        if((unsigned)gy<64u && (unsigned)gx<64u){
            float outv[RCn];
            #pragma unroll
            for(int o=0;o<RCn;o++){
                float acc = s_b[o];
                #pragma unroll
                for(int ic=0;ic<RCn;ic++){
                    const float* wr = &s_w[(o*RCn+ic)*9];
                    const float* ip = &s_in[ic*484 + oy*22 + ox];
                    #pragma unroll
                    for(int dy=0;dy<3;dy++)
                        #pragma unroll
                        for(int dx=0;dx<3;dx++)
                            acc = fmaf(wr[dy*3+dx], ip[dy*22+dx], acc);
                }
                float gv = geluf(acc);
                outv[o]=gv; sum+=gv; asum+=fabsf(gv);
            }
            if (oy>=2 && oy<18 && ox>=2 && ox<18){
                int pix = (gy<<6)+gx;
                #pragma unroll
                for(int o=0;o<RCn;o++) g_carrier[((b*RCn+o)<<12)+pix] = outv[o];
                g_densraw[(b<<12)+pix] = asum*0.125f;
            }
        }
        s_cm[i] = sum*0.125f;
        s_dr[i] = asum*0.125f;
    }
    __syncthreads();
    // hp over 18x18 (image coords ty*16-1 .. +16)
    for(int i=tid;i<324;i+=256){
        int hy=i/18, hx=i%18;
        int gy=ty*16+hy-1, gx=tx*16+hx-1;
        float hp=0.f;
        if((unsigned)gy<64u && (unsigned)gx<64u){
            int r=hy+1, c=hx+1;
            float s=0.f;
            #pragma unroll
            for(int dy=-1;dy<=1;dy++)
                #pragma unroll
                for(int dx=-1;dx<=1;dx++)
                    s += s_cm[(r+dy)*20 + c+dx];
            hp = s_cm[r*20+c] - s/9.0f;
            if (hy>=1 && hy<17 && hx>=1 && hx<17)
                g_hp[(b<<12)+(gy<<6)+gx] = hp;
        }
        s_hp[i]=hp;
    }
    __syncthreads();
    // asup interior (tid <-> 16x16)
    int ly = tid>>4, lx = tid&15;
    {
        float s=0.f;
        #pragma unroll
        for(int dy=0;dy<3;dy++)
            #pragma unroll
            for(int dx=0;dx<3;dx++)
                s += fabsf(s_hp[(ly+dy)*18 + lx+dx]);
        float a = s/9.0f;
        int gi = (b<<12) + ((ty*16+ly)<<6) + tx*16+lx;
        g_asup[gi]=a;
        float d = s_dr[(ly+2)*20 + lx+2];
        // 5 block reductions (deterministic trees)
        s_red[tid]=a; __syncthreads();
        for(int s2=128;s2>0;s2>>=1){ if(tid<s2) s_red[tid]=fminf(s_red[tid],s_red[tid+s2]); __syncthreads(); }
        float mnA=s_red[0]; __syncthreads();
        s_red[tid]=a; __syncthreads();
        for(int s2=128;s2>0;s2>>=1){ if(tid<s2) s_red[tid]=fmaxf(s_red[tid],s_red[tid+s2]); __syncthreads(); }
        float mxA=s_red[0]; __syncthreads();
        s_red[tid]=d; __syncthreads();
        for(int s2=128;s2>0;s2>>=1){ if(tid<s2) s_red[tid]=fminf(s_red[tid],s_red[tid+s2]); __syncthreads(); }
        float mnD=s_red[0]; __syncthreads();
        s_red[tid]=d; __syncthreads();
        for(int s2=128;s2>0;s2>>=1){ if(tid<s2) s_red[tid]=fmaxf(s_red[tid],s_red[tid+s2]); __syncthreads(); }
        float mxD=s_red[0]; __syncthreads();
        s_red[tid]=d; __syncthreads();
        for(int s2=128;s2>0;s2>>=1){ if(tid<s2) s_red[tid]+=s_red[tid+s2]; __syncthreads(); }
        if(tid==0){
            float* p = &g_part[(b*16 + t4)*5];
            p[0]=mnA; p[1]=mxA; p[2]=mnD; p[3]=mxD; p[4]=s_red[0];
        }
    }
}

// =====================================================================
// k_rg: responses (9x9 bank conv) + softmax-top2 + support gating +
// morphology (erode5 -> dilate9, dilate5 of gate) + blob + final ss.
// =====================================================================
__global__ void k_rg(const float* __restrict__ theta, const float* __restrict__ length,
                     const float* __restrict__ width, const float* __restrict__ plog,
                     const float* __restrict__ objn, const float* __restrict__ alpha,
                     const float* __restrict__ curv){
    __shared__ float s_k[Pp*81];
    __shared__ float s_hp[26*26];
    __shared__ float s_mask[28*28];
    __shared__ float s_g0[28*28];
    __shared__ float s_er[24*24];
    __shared__ float s_ss[18*18];
    __shared__ float s_ob[18*18];
    __shared__ float s_st[5];
    int tid=threadIdx.x;                // 256
    int blk=blockIdx.x;                 // 128
    int b = blk>>4, t4 = blk&15, ty = t4>>2, tx = t4&3;
    for(int i=tid;i<Pp*81;i+=256) s_k[i]=g_kern[i];
    if(tid==0){
        float mnA=1e30f,mxA=-1e30f,mnD=1e30f,mxD=-1e30f,sD=0.f;
        for(int t=0;t<16;t++){
            const float* p=&g_part[(b*16+t)*5];
            mnA=fminf(mnA,p[0]); mxA=fmaxf(mxA,p[1]);
            mnD=fminf(mnD,p[2]); mxD=fmaxf(mxD,p[3]); sD+=p[4];
        }
        s_st[0]=mnA; s_st[1]=mxA; s_st[2]=mnD; s_st[3]=mxD; s_st[4]=sD/(float)HW;
    }
    for(int i=tid;i<676;i+=256){
        int r=i/26,c=i%26;
        int gy=ty*16+r-5, gx=tx*16+c-5;
        float v=0.f;
        if((unsigned)gy<64u && (unsigned)gx<64u) v=g_hp[(b<<12)+(gy<<6)+gx];
        s_hp[i]=v;
    }
    __syncthreads();
    float mnA=s_st[0],mxA=s_st[1],mnD=s_st[2],mxD=s_st[3],meanD=s_st[4];
    float mC = fmaxf(meanD,1e-6f);
    float dmn = mnD/mC, dmx = mxD/mC;
    float invA = 1.0f/fmaxf(mxA-mnA,1e-6f);
    float invD = 1.0f/fmaxf(dmx-dmn,1e-6f);
    // ev/mask/gate0 over 28x28 (halo 6)
    for(int i=tid;i<784;i+=256){
        int r=i/28,c=i%28;
        int gy=ty*16+r-6, gx=tx*16+c-6;
        float mv=1.0f, g0=0.0f;
        if((unsigned)gy<64u && (unsigned)gx<64u){
            int gi=(b<<12)+(gy<<6)+gx;
            float csup = (g_asup[gi]-mnA)*invA;
            float dsup = (g_densraw[gi]/mC - dmn)*invD;
            float ev = 0.65f*csup + 0.35f*dsup;
            mv = (ev>=0.2f)?1.0f:0.0f;
            g0 = sigmf((ev-0.2f)*12.5f);
        }
        s_mask[i]=mv; s_g0[i]=g0;
    }
    // ss1 over 18x18 (halo 1) + objectness
    const float COSO[8]={1.0f,0.70710678f,0.0f,-0.70710678f,-1.0f,-0.70710678f,0.0f,0.70710678f};
    const float SINO[8]={0.0f,0.70710678f,1.0f,0.70710678f,0.0f,-0.70710678f,-1.0f,-0.70710678f};
    const float LA[8]={0.45f,0.75f,1.05f,0.45f,0.75f,1.05f,0.45f,0.75f};
    const float WA[8]={0.14f,0.14f,0.14f,0.2f,0.2f,0.2f,0.28f,0.28f};
    __syncthreads();
    for(int i=tid;i<324;i+=256){
        int sy=i/18, sx=i%18;
        int gy=ty*16+sy-1, gx=tx*16+sx-1;
        float ssv=0.f, ov=0.f;
        if((unsigned)gy<64u && (unsigned)gx<64u){
            int gi=(b<<12)+(gy<<6)+gx;
            float resp[Pp];
            #pragma unroll
            for(int p=0;p<Pp;p++) resp[p]=0.f;
            #pragma unroll
            for(int dy=0;dy<9;dy++){
                #pragma unroll
                for(int dx=0;dx<9;dx++){
                    float hv = s_hp[(sy+dy)*26 + sx+dx];
                    int off = dy*9+dx;
                    #pragma unroll
                    for(int p=0;p<Pp;p++) resp[p]=fmaf(s_k[p*81+off],hv,resp[p]);
                }
            }
            float th = tanhf(theta[gi])*3.14159265358979f;
            float sth, cth; sincosf(th,&sth,&cth);
            float lv = sigmf(length[gi])*0.85f + 0.25f;
            float wv = sigmf(width[gi]) *0.22f + 0.08f;
            float bias[8];
            #pragma unroll
            for(int p=0;p<8;p++){
                float ts = cth*COSO[p] + sth*SINO[p];
                float dl = lv - LA[p];
                float dw = wv - WA[p];
                bias[p] = plog[((b*8+p)<<12) + (gy<<6)+gx] + 1.25f*ts - dl*dl*12.5f - dw*dw*100.0f;
            }
            int i1=0; float b1=bias[0];
            #pragma unroll
            for(int p=1;p<8;p++) if(bias[p]>b1){b1=bias[p];i1=p;}
            int i2=-1; float b2=-1e30f;
            #pragma unroll
            for(int p=0;p<8;p++){ if(p==i1) continue; if(bias[p]>b2){b2=bias[p];i2=p;} }
            float e = expf(b2-b1);
            float w1 = 1.0f/(1.0f+e);
            float w2 = e/(1.0f+e);
            #pragma unroll
            for(int p=0;p<8;p++){
                float wp = (p==i1)?w1:((p==i2)?w2:0.f);
                ssv = fmaf(wp, resp[p], ssv);
            }
            ov = sigmf(objn[gi]);
        }
        s_ss[i]=ssv; s_ob[i]=ov;
    }
    __syncthreads();
    // erosion 5x5 over 24x24 (halo 4)
    for(int i=tid;i<576;i+=256){
        int ey=i/24, ex=i%24;
        int gy=ty*16+ey-4, gx=tx*16+ex-4;
        float m=0.f;
        if((unsigned)gy<64u && (unsigned)gx<64u){
            m=1.0f;
            #pragma unroll
            for(int dy=0;dy<5;dy++)
                #pragma unroll
                for(int dx=0;dx<5;dx++)
                    m=fminf(m, s_mask[(ey+dy)*28 + ex+dx]);
        }
        s_er[i]=m;
    }
    __syncthreads();
    // final 16x16
    int ly=tid>>4, lx=tid&15;
    float m9=0.f;
    #pragma unroll
    for(int dy=0;dy<9;dy++)
        #pragma unroll
        for(int dx=0;dx<9;dx++)
            m9=fmaxf(m9, s_er[(ly+dy)*24 + lx+dx]);
    float g5=0.f;
    #pragma unroll
    for(int dy=0;dy<5;dy++)
        #pragma unroll
        for(int dx=0;dx<5;dx++)
            g5=fmaxf(g5, s_g0[(ly+4+dy)*28 + lx+4+dx]);
    float gate = g5*m9;
    float so=0.f, sv=0.f;
    #pragma unroll
    for(int dy=0;dy<3;dy++)
        #pragma unroll
        for(int dx=0;dx<3;dx++){
            so += s_ob[(ly+dy)*18 + lx+dx];
            sv += s_ss[(ly+dy)*18 + lx+dx];
        }
    float blob = (so/9.0f)*gate;
    float ss2 = s_ss[(ly+1)*18 + lx+1] - sv/9.0f;
    int gi = (b<<12) + ((ty*16+ly)<<6) + tx*16+lx;
    float d = g_densraw[gi]/mC;
    float sg = sigmf(alpha[gi])*blob*(0.7f + 0.3f*fminf(fmaxf(d,0.f),2.0f));
    g_ssf[gi] = sg*ss2*(1.0f + 0.15f*tanhf(curv[gi]));
}

// =====================================================================
// k_out: feats -> pm1+gelu -> pm2. 2-way output-channel split per block.
// =====================================================================
__global__ void k_out(const float* __restrict__ theta, const float* __restrict__ curv,
                      const float* __restrict__ pm1w, const float* __restrict__ pm1b,
                      const float* __restrict__ pm2w, const float* __restrict__ pm2b,
                      float* __restrict__ out){
    __shared__ float s_p2[384*RCn];   // 12KB, this half's weights [o][k]
    __shared__ float s_b2[384];
    __shared__ float s_p1[RCn*12];
    __shared__ float s_b1[RCn];
    int tid = threadIdx.x;            // 256
    int pb   = blockIdx.x >> 1;       // pixel block (0..127)
    int half = blockIdx.x & 1;        // output-channel half
    for(int i=tid;i<384*RCn;i+=256) s_p2[i]=pm2w[half*384*RCn + i];
    for(int i=tid;i<384;i+=256) s_b2[i]=pm2b[half*384 + i];
    if(tid<RCn*12) s_p1[tid]=pm1w[tid];
    if(tid<RCn) s_b1[tid]=pm1b[tid];
    __syncthreads();
    int g = pb*256 + tid;
    int b = g>>12, pix = g&4095;
    float ss = g_ssf[g];
    float th = tanhf(theta[g])*3.14159265358979f;
    float sth, cth; sincosf(th,&sth,&cth);
    float cv = tanhf(curv[g]);
    float f[12];
    #pragma unroll
    for(int o=0;o<RCn;o++) f[o] = g_carrier[((b*RCn+o)<<12)+pix]*ss;
    f[8]=ss; f[9]=cth*ss; f[10]=sth*ss; f[11]=cv*ss;
    float h[RCn];
    #pragma unroll
    for(int o=0;o<RCn;o++){
        float acc = s_b1[o];
        #pragma unroll
        for(int j=0;j<12;j++) acc = fmaf(s_p1[o*12+j], f[j], acc);
        h[o]=geluf(acc);
    }
    float* op = out + ((size_t)b*FCn<<12) + ((size_t)(half*384)<<12) + pix;
    #pragma unroll 4
    for(int o=0;o<384;o++){
        const float* wr = &s_p2[o*RCn];
        float acc = s_b2[o];
        #pragma unroll
        for(int k=0;k<RCn;k++) acc = fmaf(wr[k], h[k], acc);
        op[(size_t)o<<12] = acc;
    }
}

extern "C" void kernel_launch(void* const* d_in, const int* in_sizes, int n_in,
                              void* d_out, int out_size){
    const float* fm     = (const float*)d_in[0];
    const float* theta  = (const float*)d_in[1];
    const float* length = (const float*)d_in[2];
    const float* width  = (const float*)d_in[3];
    const float* curv   = (const float*)d_in[4];
    const float* alpha  = (const float*)d_in[5];
    const float* objn   = (const float*)d_in[6];
    const float* plog   = (const float*)d_in[7];
    const float* fp1w   = (const float*)d_in[8];
    const float* fp1b   = (const float*)d_in[9];
    const float* fp2w   = (const float*)d_in[10];
    const float* fp2b   = (const float*)d_in[11];
    const float* pm1w   = (const float*)d_in[12];
    const float* pm1b   = (const float*)d_in[13];
    const float* pm2w   = (const float*)d_in[14];
    const float* pm2b   = (const float*)d_in[15];
    const float* pd     = (const float*)d_in[16];
    float* out = (float*)d_out;

    k_conv1  <<<256, 256>>>(fm, fp1w, fp1b, pd);
    k_conv3hp<<<128, 256>>>(fp2w, fp2b);
    k_rg     <<<128, 256>>>(theta, length, width, plog, objn, alpha, curv);
    k_out    <<<256, 256>>>(theta, curv, pm1w, pm1b, pm2w, pm2b, out);
}

// round 3
// speedup vs baseline: 1.5324x; 1.3395x over previous
#include <cuda_runtime.h>
#include <math.h>

#define Pp 8
#define RCn 8
#define FCn 768
#define Bb 8
#define HW 4096

// ---------------- scratch (device globals; no allocation) ----------------
__device__ float g_kern[Pp*81];
__device__ float g_c1[Bb*RCn*HW];
__device__ float g_carrier[Bb*RCn*HW];
__device__ float g_densraw[Bb*HW];
__device__ float g_hp[Bb*HW];
__device__ float g_asup[Bb*HW];
__device__ float g_part[Bb*16*5];   // per-tile partials: mnA,mxA,mnD,mxD,sumD
__device__ float g_h[RCn*Bb*HW];    // hidden after pm1+gelu, channel-major

__device__ __forceinline__ float geluf(float x){ return 0.5f*x*(1.0f+erff(x*0.70710678118654752f)); }
__device__ __forceinline__ float sigmf(float x){ return 1.0f/(1.0f+expf(-x)); }

// =====================================================================
// k_conv1: 1x1 conv 768->8 + gelu. float4 pixels, 8-way channel split.
// 256 blocks x 256 threads; block = 128 pixels (32 float4 groups).
// Blocks 0..7 additionally build the filter bank.
// =====================================================================
__global__ void k_conv1(const float* __restrict__ fm,
                        const float* __restrict__ w,
                        const float* __restrict__ bias,
                        const float* __restrict__ pd){
    __shared__ float sw[FCn*RCn];          // [c][o] 24KB
    __shared__ float4 s_part[7*32*RCn];    // partials from splits 1..7, 28KB
    __shared__ float s_red[256];
    int tid = threadIdx.x;                 // 256
    for(int idx = tid; idx < FCn*RCn; idx += 256){
        int o = idx / FCn, c = idx % FCn;
        sw[c*RCn + o] = w[idx];
    }
    __syncthreads();
    int lane = tid & 31;                   // float4 pixel group within block
    int sp   = tid >> 5;                   // channel split 0..7 (96 ch each)
    int g4 = blockIdx.x*32 + lane;         // global float4 group (0..8191)
    int b = g4 >> 10;
    int pix = (g4 << 2) & 4095;
    const float* xp = fm + ((size_t)b*FCn + sp*96)*HW + pix;
    float4 acc[RCn];
    #pragma unroll
    for(int o=0;o<RCn;o++){ acc[o].x=0.f; acc[o].y=0.f; acc[o].z=0.f; acc[o].w=0.f; }
    #pragma unroll 4
    for(int c=0;c<96;c++){
        float4 xv = __ldg((const float4*)(xp + (size_t)c*HW));
        const float* wr = &sw[(sp*96 + c)*RCn];
        #pragma unroll
        for(int o=0;o<RCn;o++){
            float wv = wr[o];
            acc[o].x = fmaf(xv.x, wv, acc[o].x);
            acc[o].y = fmaf(xv.y, wv, acc[o].y);
            acc[o].z = fmaf(xv.z, wv, acc[o].z);
            acc[o].w = fmaf(xv.w, wv, acc[o].w);
        }
    }
    if (sp > 0){
        #pragma unroll
        for(int o=0;o<RCn;o++) s_part[((sp-1)*32 + lane)*RCn + o] = acc[o];
    }
    __syncthreads();
    if (sp == 0){
        #pragma unroll
        for(int o=0;o<RCn;o++){
            float4 a = acc[o];
            #pragma unroll
            for(int q=0;q<7;q++){
                float4 p = s_part[(q*32 + lane)*RCn + o];
                a.x+=p.x; a.y+=p.y; a.z+=p.z; a.w+=p.w;
            }
            float bo = bias[o];
            float4 r;
            r.x = geluf(a.x+bo); r.y = geluf(a.y+bo);
            r.z = geluf(a.z+bo); r.w = geluf(a.w+bo);
            *(float4*)&g_c1[((b*RCn+o)<<12) + pix] = r;
        }
    }
    // ---- filter bank (blocks 0..7) ----
    if (blockIdx.x < 8){
        int i = blockIdx.x;
        float ridge = 0.f;
        if (tid < 81){
            int r = tid/9, c = tid%9;
            float y = -1.0f + 0.25f*(float)r;
            float x = -1.0f + 0.25f*(float)c;
            double angd = 6.283185307179586476925286766559 * (double)i / 8.0;
            const float Ls[3] = {0.45f,0.75f,1.05f};
            const float Ws[3] = {0.14f,0.2f,0.28f};
            float L = Ls[i%3], Wd = Ws[(i/3)%3];
            float ca = (float)cos(angd), sa = (float)sin(angd);
            float xr =  x*ca + y*sa;
            float yr = -x*sa + y*ca;
            float tpr = 1.0f - fminf(fabsf(xr)/L, 1.0f);
            tpr = tpr*sqrtf(tpr);
            float ax = xr/L, ay = yr/Wd;
            float core = expf(-0.5f*(ax*ax + ay*ay));
            float lobe = fmaxf(1.0f - ay*ay, 0.0f);
            ridge = tpr*core*lobe;
        }
        __syncthreads();
        s_red[tid] = (tid<81)? ridge : 0.f;
        __syncthreads();
        for(int s=128;s>0;s>>=1){ if(tid<s) s_red[tid]+=s_red[tid+s]; __syncthreads(); }
        float mean = s_red[0]/81.0f;
        __syncthreads();
        float kv = (tid<81)? (ridge-mean) : 0.f;
        s_red[tid] = fabsf(kv);
        __syncthreads();
        for(int s=128;s>0;s>>=1){ if(tid<s) s_red[tid]+=s_red[tid+s]; __syncthreads(); }
        float nrm = fmaxf(s_red[0], 1e-6f);
        if (tid<81) g_kern[i*81+tid] = kv/nrm + 0.05f*pd[i*81+tid];
    }
}

// =====================================================================
// k_conv3hp: 3x3 conv 8->8 + gelu over halo region, carrier store,
// cmean/hp/asup/densraw + per-tile stat partials.
// =====================================================================
__global__ void k_conv3hp(const float* __restrict__ w, const float* __restrict__ bias){
    __shared__ float s_in[RCn*22*22];
    __shared__ float s_w[RCn*RCn*9];
    __shared__ float s_b[RCn];
    __shared__ float s_cm[20*20];
    __shared__ float s_dr[20*20];
    __shared__ float s_hp[18*18];
    __shared__ float s_red[256];
    int tid = threadIdx.x;              // 256
    int blk = blockIdx.x;               // 128
    int b = blk >> 4;
    int t4 = blk & 15, ty = t4 >> 2, tx = t4 & 3;
    for(int idx=tid; idx<RCn*RCn*9; idx+=256) s_w[idx]=w[idx];
    if (tid < RCn) s_b[tid]=bias[tid];
    for(int idx=tid; idx<RCn*484; idx+=256){
        int ch = idx/484, rem = idx%484;
        int r = rem/22, c = rem%22;
        int gy = ty*16 + r - 3, gx = tx*16 + c - 3;
        float v = 0.f;
        if ((unsigned)gy<64u && (unsigned)gx<64u)
            v = g_c1[((b*RCn+ch)<<12) + (gy<<6) + gx];
        s_in[ch*484 + r*22 + c] = v;
    }
    __syncthreads();
    for(int i=tid; i<400; i+=256){
        int oy=i/20, ox=i%20;
        int gy=ty*16+oy-2, gx=tx*16+ox-2;
        float sum=0.f, asum=0.f;
        if((unsigned)gy<64u && (unsigned)gx<64u){
            float outv[RCn];
            #pragma unroll
            for(int o=0;o<RCn;o++){
                float acc = s_b[o];
                #pragma unroll
                for(int ic=0;ic<RCn;ic++){
                    const float* wr = &s_w[(o*RCn+ic)*9];
                    const float* ip = &s_in[ic*484 + oy*22 + ox];
                    #pragma unroll
                    for(int dy=0;dy<3;dy++)
                        #pragma unroll
                        for(int dx=0;dx<3;dx++)
                            acc = fmaf(wr[dy*3+dx], ip[dy*22+dx], acc);
                }
                float gv = geluf(acc);
                outv[o]=gv; sum+=gv; asum+=fabsf(gv);
            }
            if (oy>=2 && oy<18 && ox>=2 && ox<18){
                int pix = (gy<<6)+gx;
                #pragma unroll
                for(int o=0;o<RCn;o++) g_carrier[((b*RCn+o)<<12)+pix] = outv[o];
                g_densraw[(b<<12)+pix] = asum*0.125f;
            }
        }
        s_cm[i] = sum*0.125f;
        s_dr[i] = asum*0.125f;
    }
    __syncthreads();
    for(int i=tid;i<324;i+=256){
        int hy=i/18, hx=i%18;
        int gy=ty*16+hy-1, gx=tx*16+hx-1;
        float hp=0.f;
        if((unsigned)gy<64u && (unsigned)gx<64u){
            int r=hy+1, c=hx+1;
            float s=0.f;
            #pragma unroll
            for(int dy=-1;dy<=1;dy++)
                #pragma unroll
                for(int dx=-1;dx<=1;dx++)
                    s += s_cm[(r+dy)*20 + c+dx];
            hp = s_cm[r*20+c] - s/9.0f;
            if (hy>=1 && hy<17 && hx>=1 && hx<17)
                g_hp[(b<<12)+(gy<<6)+gx] = hp;
        }
        s_hp[i]=hp;
    }
    __syncthreads();
    int ly = tid>>4, lx = tid&15;
    {
        float s=0.f;
        #pragma unroll
        for(int dy=0;dy<3;dy++)
            #pragma unroll
            for(int dx=0;dx<3;dx++)
                s += fabsf(s_hp[(ly+dy)*18 + lx+dx]);
        float a = s/9.0f;
        int gi = (b<<12) + ((ty*16+ly)<<6) + tx*16+lx;
        g_asup[gi]=a;
        float d = s_dr[(ly+2)*20 + lx+2];
        s_red[tid]=a; __syncthreads();
        for(int s2=128;s2>0;s2>>=1){ if(tid<s2) s_red[tid]=fminf(s_red[tid],s_red[tid+s2]); __syncthreads(); }
        float mnA=s_red[0]; __syncthreads();
        s_red[tid]=a; __syncthreads();
        for(int s2=128;s2>0;s2>>=1){ if(tid<s2) s_red[tid]=fmaxf(s_red[tid],s_red[tid+s2]); __syncthreads(); }
        float mxA=s_red[0]; __syncthreads();
        s_red[tid]=d; __syncthreads();
        for(int s2=128;s2>0;s2>>=1){ if(tid<s2) s_red[tid]=fminf(s_red[tid],s_red[tid+s2]); __syncthreads(); }
        float mnD=s_red[0]; __syncthreads();
        s_red[tid]=d; __syncthreads();
        for(int s2=128;s2>0;s2>>=1){ if(tid<s2) s_red[tid]=fmaxf(s_red[tid],s_red[tid+s2]); __syncthreads(); }
        float mxD=s_red[0]; __syncthreads();
        s_red[tid]=d; __syncthreads();
        for(int s2=128;s2>0;s2>>=1){ if(tid<s2) s_red[tid]+=s_red[tid+s2]; __syncthreads(); }
        if(tid==0){
            float* p = &g_part[(b*16 + t4)*5];
            p[0]=mnA; p[1]=mxA; p[2]=mnD; p[3]=mxD; p[4]=s_red[0];
        }
    }
}

// =====================================================================
// k_rg: 9x9 bank conv + softmax-top2 + gating + morphology + final ss
// + feats -> pm1 + gelu -> g_h (channel-major hidden).
// =====================================================================
__global__ void k_rg(const float* __restrict__ theta, const float* __restrict__ length,
                     const float* __restrict__ width, const float* __restrict__ plog,
                     const float* __restrict__ objn, const float* __restrict__ alpha,
                     const float* __restrict__ curv,
                     const float* __restrict__ pm1w, const float* __restrict__ pm1b){
    __shared__ float s_k[Pp*81];
    __shared__ float s_hp[26*26];
    __shared__ float s_mask[28*28];
    __shared__ float s_g0[28*28];
    __shared__ float s_er[24*24];
    __shared__ float s_ss[18*18];
    __shared__ float s_ob[18*18];
    __shared__ float s_st[5];
    __shared__ float s_p1[RCn*12];
    __shared__ float s_b1[RCn];
    int tid=threadIdx.x;                // 256
    int blk=blockIdx.x;                 // 128
    int b = blk>>4, t4 = blk&15, ty = t4>>2, tx = t4&3;
    for(int i=tid;i<Pp*81;i+=256) s_k[i]=g_kern[i];
    if(tid<RCn*12) s_p1[tid]=pm1w[tid];
    if(tid<RCn) s_b1[tid]=pm1b[tid];
    if(tid==0){
        float mnA=1e30f,mxA=-1e30f,mnD=1e30f,mxD=-1e30f,sD=0.f;
        for(int t=0;t<16;t++){
            const float* p=&g_part[(b*16+t)*5];
            mnA=fminf(mnA,p[0]); mxA=fmaxf(mxA,p[1]);
            mnD=fminf(mnD,p[2]); mxD=fmaxf(mxD,p[3]); sD+=p[4];
        }
        s_st[0]=mnA; s_st[1]=mxA; s_st[2]=mnD; s_st[3]=mxD; s_st[4]=sD/(float)HW;
    }
    for(int i=tid;i<676;i+=256){
        int r=i/26,c=i%26;
        int gy=ty*16+r-5, gx=tx*16+c-5;
        float v=0.f;
        if((unsigned)gy<64u && (unsigned)gx<64u) v=g_hp[(b<<12)+(gy<<6)+gx];
        s_hp[i]=v;
    }
    __syncthreads();
    float mnA=s_st[0],mxA=s_st[1],mnD=s_st[2],mxD=s_st[3],meanD=s_st[4];
    float mC = fmaxf(meanD,1e-6f);
    float dmn = mnD/mC, dmx = mxD/mC;
    float invA = 1.0f/fmaxf(mxA-mnA,1e-6f);
    float invD = 1.0f/fmaxf(dmx-dmn,1e-6f);
    for(int i=tid;i<784;i+=256){
        int r=i/28,c=i%28;
        int gy=ty*16+r-6, gx=tx*16+c-6;
        float mv=1.0f, g0=0.0f;
        if((unsigned)gy<64u && (unsigned)gx<64u){
            int gi=(b<<12)+(gy<<6)+gx;
            float csup = (g_asup[gi]-mnA)*invA;
            float dsup = (g_densraw[gi]/mC - dmn)*invD;
            float ev = 0.65f*csup + 0.35f*dsup;
            mv = (ev>=0.2f)?1.0f:0.0f;
            g0 = sigmf((ev-0.2f)*12.5f);
        }
        s_mask[i]=mv; s_g0[i]=g0;
    }
    const float COSO[8]={1.0f,0.70710678f,0.0f,-0.70710678f,-1.0f,-0.70710678f,0.0f,0.70710678f};
    const float SINO[8]={0.0f,0.70710678f,1.0f,0.70710678f,0.0f,-0.70710678f,-1.0f,-0.70710678f};
    const float LA[8]={0.45f,0.75f,1.05f,0.45f,0.75f,1.05f,0.45f,0.75f};
    const float WA[8]={0.14f,0.14f,0.14f,0.2f,0.2f,0.2f,0.28f,0.28f};
    __syncthreads();
    for(int i=tid;i<324;i+=256){
        int sy=i/18, sx=i%18;
        int gy=ty*16+sy-1, gx=tx*16+sx-1;
        float ssv=0.f, ov=0.f;
        if((unsigned)gy<64u && (unsigned)gx<64u){
            int gi=(b<<12)+(gy<<6)+gx;
            float resp[Pp];
            #pragma unroll
            for(int p=0;p<Pp;p++) resp[p]=0.f;
            #pragma unroll
            for(int dy=0;dy<9;dy++){
                #pragma unroll
                for(int dx=0;dx<9;dx++){
                    float hv = s_hp[(sy+dy)*26 + sx+dx];
                    int off = dy*9+dx;
                    #pragma unroll
                    for(int p=0;p<Pp;p++) resp[p]=fmaf(s_k[p*81+off],hv,resp[p]);
                }
            }
            float th = tanhf(theta[gi])*3.14159265358979f;
            float sth, cth; sincosf(th,&sth,&cth);
            float lv = sigmf(length[gi])*0.85f + 0.25f;
            float wv = sigmf(width[gi]) *0.22f + 0.08f;
            float bias[8];
            #pragma unroll
            for(int p=0;p<8;p++){
                float ts = cth*COSO[p] + sth*SINO[p];
                float dl = lv - LA[p];
                float dw = wv - WA[p];
                bias[p] = plog[((b*8+p)<<12) + (gy<<6)+gx] + 1.25f*ts - dl*dl*12.5f - dw*dw*100.0f;
            }
            int i1=0; float b1=bias[0];
            #pragma unroll
            for(int p=1;p<8;p++) if(bias[p]>b1){b1=bias[p];i1=p;}
            int i2=-1; float b2=-1e30f;
            #pragma unroll
            for(int p=0;p<8;p++){ if(p==i1) continue; if(bias[p]>b2){b2=bias[p];i2=p;} }
            float e = expf(b2-b1);
            float w1 = 1.0f/(1.0f+e);
            float w2 = e/(1.0f+e);
            #pragma unroll
            for(int p=0;p<8;p++){
                float wp = (p==i1)?w1:((p==i2)?w2:0.f);
                ssv = fmaf(wp, resp[p], ssv);
            }
            ov = sigmf(objn[gi]);
        }
        s_ss[i]=ssv; s_ob[i]=ov;
    }
    __syncthreads();
    for(int i=tid;i<576;i+=256){
        int ey=i/24, ex=i%24;
        int gy=ty*16+ey-4, gx=tx*16+ex-4;
        float m=0.f;
        if((unsigned)gy<64u && (unsigned)gx<64u){
            m=1.0f;
            #pragma unroll
            for(int dy=0;dy<5;dy++)
                #pragma unroll
                for(int dx=0;dx<5;dx++)
                    m=fminf(m, s_mask[(ey+dy)*28 + ex+dx]);
        }
        s_er[i]=m;
    }
    __syncthreads();
    int ly=tid>>4, lx=tid&15;
    float m9=0.f;
    #pragma unroll
    for(int dy=0;dy<9;dy++)
        #pragma unroll
        for(int dx=0;dx<9;dx++)
            m9=fmaxf(m9, s_er[(ly+dy)*24 + lx+dx]);
    float g5=0.f;
    #pragma unroll
    for(int dy=0;dy<5;dy++)
        #pragma unroll
        for(int dx=0;dx<5;dx++)
            g5=fmaxf(g5, s_g0[(ly+4+dy)*28 + lx+4+dx]);
    float gate = g5*m9;
    float so=0.f, sv=0.f;
    #pragma unroll
    for(int dy=0;dy<3;dy++)
        #pragma unroll
        for(int dx=0;dx<3;dx++){
            so += s_ob[(ly+dy)*18 + lx+dx];
            sv += s_ss[(ly+dy)*18 + lx+dx];
        }
    float blob = (so/9.0f)*gate;
    float ss2 = s_ss[(ly+1)*18 + lx+1] - sv/9.0f;
    int gi = (b<<12) + ((ty*16+ly)<<6) + tx*16+lx;
    float d = g_densraw[gi]/mC;
    float cv = tanhf(curv[gi]);
    float sg = sigmf(alpha[gi])*blob*(0.7f + 0.3f*fminf(fmaxf(d,0.f),2.0f));
    float ssf = sg*ss2*(1.0f + 0.15f*cv);
    // pm1 + gelu -> g_h
    float th2 = tanhf(theta[gi])*3.14159265358979f;
    float sth2, cth2; sincosf(th2,&sth2,&cth2);
    float f[12];
    #pragma unroll
    for(int o=0;o<RCn;o++) f[o] = g_carrier[((b*RCn+o)<<12) + (gi&4095)]*ssf;
    f[8]=ssf; f[9]=cth2*ssf; f[10]=sth2*ssf; f[11]=cv*ssf;
    #pragma unroll
    for(int o=0;o<RCn;o++){
        float acc = s_b1[o];
        #pragma unroll
        for(int j=0;j<12;j++) acc = fmaf(s_p1[o*12+j], f[j], acc);
        g_h[(o<<15) + gi] = geluf(acc);
    }
}

// =====================================================================
// k_out: pure GEMV 8 -> 768 with float4 pixels + float4 stores.
// 256 blocks (32 pixel-blocks x 8 channel splits) x 256 threads.
// =====================================================================
__global__ void k_out(const float* __restrict__ pm2w, const float* __restrict__ pm2b,
                      float* __restrict__ out){
    __shared__ float s_w[96*RCn];     // 3KB
    __shared__ float s_b[96];
    int tid = threadIdx.x;            // 256
    int pb = blockIdx.x >> 3;         // pixel block 0..31
    int sp = blockIdx.x & 7;          // channel split 0..7 (96 out ch)
    for(int i=tid;i<96*RCn;i+=256) s_w[i]=pm2w[sp*96*RCn + i];
    if(tid<96) s_b[tid]=pm2b[sp*96 + tid];
    __syncthreads();
    int g4 = pb*256 + tid;            // float4 pixel group, 0..8191
    int b = g4 >> 10;
    int pix = (g4 << 2) & 4095;
    float4 h4[RCn];
    #pragma unroll
    for(int k=0;k<RCn;k++) h4[k] = __ldg((const float4*)&g_h[(k<<15) + (g4<<2)]);
    float* op = out + ((size_t)b*FCn + sp*96)*HW + pix;
    #pragma unroll 4
    for(int o=0;o<96;o++){
        const float* wr = &s_w[o*RCn];
        float bo = s_b[o];
        float4 a; a.x=bo; a.y=bo; a.z=bo; a.w=bo;
        #pragma unroll
        for(int k=0;k<RCn;k++){
            float wv = wr[k];
            a.x = fmaf(wv, h4[k].x, a.x);
            a.y = fmaf(wv, h4[k].y, a.y);
            a.z = fmaf(wv, h4[k].z, a.z);
            a.w = fmaf(wv, h4[k].w, a.w);
        }
        *(float4*)(op + (size_t)o*HW) = a;
    }
}

extern "C" void kernel_launch(void* const* d_in, const int* in_sizes, int n_in,
                              void* d_out, int out_size){
    const float* fm     = (const float*)d_in[0];
    const float* theta  = (const float*)d_in[1];
    const float* length = (const float*)d_in[2];
    const float* width  = (const float*)d_in[3];
    const float* curv   = (const float*)d_in[4];
    const float* alpha  = (const float*)d_in[5];
    const float* objn   = (const float*)d_in[6];
    const float* plog   = (const float*)d_in[7];
    const float* fp1w   = (const float*)d_in[8];
    const float* fp1b   = (const float*)d_in[9];
    const float* fp2w   = (const float*)d_in[10];
    const float* fp2b   = (const float*)d_in[11];
    const float* pm1w   = (const float*)d_in[12];
    const float* pm1b   = (const float*)d_in[13];
    const float* pm2w   = (const float*)d_in[14];
    const float* pm2b   = (const float*)d_in[15];
    const float* pd     = (const float*)d_in[16];
    float* out = (float*)d_out;

    k_conv1  <<<256, 256>>>(fm, fp1w, fp1b, pd);
    k_conv3hp<<<128, 256>>>(fp2w, fp2b);
    k_rg     <<<128, 256>>>(theta, length, width, plog, objn, alpha, curv, pm1w, pm1b);
    k_out    <<<256, 256>>>(pm2w, pm2b, out);
}

// round 6
// speedup vs baseline: 1.6737x; 1.0922x over previous
#include <cuda_runtime.h>
#include <math.h>

#define Pp 8
#define RCn 8
#define FCn 768
#define Bb 8
#define HW 4096

// ---------------- scratch (device globals; no allocation) ----------------
__device__ float g_kern[Pp*81];
__device__ float g_c1[Bb*RCn*HW];
__device__ float g_carrier[Bb*RCn*HW];
__device__ float g_densraw[Bb*HW];
__device__ float g_hp[Bb*HW];
__device__ float g_asup[Bb*HW];
__device__ float g_part[Bb*32*5];   // per-tile partials: mnA,mxA,mnD,mxD,sumD
__device__ float g_h[RCn*Bb*HW];    // hidden after pm1+gelu, channel-major

__device__ __forceinline__ float geluf(float x){ return 0.5f*x*(1.0f+erff(x*0.70710678118654752f)); }
__device__ __forceinline__ float sigmf(float x){ return 1.0f/(1.0f+expf(-x)); }

// =====================================================================
// k_conv1: 1x1 conv 768->8 + gelu. float4 pixels, 16-way channel split.
// 512 blocks x 256 threads; block = 64 pixels (16 float4 groups).
// Blocks 0..7 additionally build the filter bank.
// =====================================================================
__global__ void k_conv1(const float* __restrict__ fm,
                        const float* __restrict__ w,
                        const float* __restrict__ bias,
                        const float* __restrict__ pd){
    __shared__ float sw[FCn*RCn];           // [c][o] 24KB
    __shared__ float4 s_part[15*16*RCn];    // partials from splits 1..15, 30KB
    __shared__ float s_red[256];
    int tid = threadIdx.x;                  // 256
    for(int idx = tid; idx < FCn*RCn; idx += 256){
        int o = idx / FCn, c = idx % FCn;
        sw[c*RCn + o] = w[idx];
    }
    __syncthreads();
    int lane = tid & 15;                    // float4 pixel group within block
    int sp   = tid >> 4;                    // channel split 0..15 (48 ch each)
    int g4 = blockIdx.x*16 + lane;          // global float4 group (0..8191)
    int b = g4 >> 10;
    int pix = (g4 << 2) & 4095;
    const float* xp = fm + ((size_t)b*FCn + sp*48)*HW + pix;
    float4 acc[RCn];
    #pragma unroll
    for(int o=0;o<RCn;o++){ acc[o].x=0.f; acc[o].y=0.f; acc[o].z=0.f; acc[o].w=0.f; }
    #pragma unroll 4
    for(int c=0;c<48;c++){
        float4 xv = __ldg((const float4*)(xp + (size_t)c*HW));
        const float* wr = &sw[(sp*48 + c)*RCn];
        #pragma unroll
        for(int o=0;o<RCn;o++){
            float wv = wr[o];
            acc[o].x = fmaf(xv.x, wv, acc[o].x);
            acc[o].y = fmaf(xv.y, wv, acc[o].y);
            acc[o].z = fmaf(xv.z, wv, acc[o].z);
            acc[o].w = fmaf(xv.w, wv, acc[o].w);
        }
    }
    if (sp > 0){
        #pragma unroll
        for(int o=0;o<RCn;o++) s_part[((sp-1)*16 + lane)*RCn + o] = acc[o];
    }
    __syncthreads();
    if (sp == 0){
        #pragma unroll
        for(int o=0;o<RCn;o++){
            float4 a = acc[o];
            #pragma unroll
            for(int q=0;q<15;q++){
                float4 p = s_part[(q*16 + lane)*RCn + o];
                a.x+=p.x; a.y+=p.y; a.z+=p.z; a.w+=p.w;
            }
            float bo = bias[o];
            float4 r;
            r.x = geluf(a.x+bo); r.y = geluf(a.y+bo);
            r.z = geluf(a.z+bo); r.w = geluf(a.w+bo);
            *(float4*)&g_c1[((b*RCn+o)<<12) + pix] = r;
        }
    }
    // ---- filter bank (blocks 0..7) ----
    if (blockIdx.x < 8){
        int i = blockIdx.x;
        float ridge = 0.f;
        if (tid < 81){
            int r = tid/9, c = tid%9;
            float y = -1.0f + 0.25f*(float)r;
            float x = -1.0f + 0.25f*(float)c;
            double angd = 6.283185307179586476925286766559 * (double)i / 8.0;
            const float Ls[3] = {0.45f,0.75f,1.05f};
            const float Ws[3] = {0.14f,0.2f,0.28f};
            float L = Ls[i%3], Wd = Ws[(i/3)%3];
            float ca = (float)cos(angd), sa = (float)sin(angd);
            float xr =  x*ca + y*sa;
            float yr = -x*sa + y*ca;
            float tpr = 1.0f - fminf(fabsf(xr)/L, 1.0f);
            tpr = tpr*sqrtf(tpr);
            float ax = xr/L, ay = yr/Wd;
            float core = expf(-0.5f*(ax*ax + ay*ay));
            float lobe = fmaxf(1.0f - ay*ay, 0.0f);
            ridge = tpr*core*lobe;
        }
        __syncthreads();
        s_red[tid] = (tid<81)? ridge : 0.f;
        __syncthreads();
        for(int s=128;s>0;s>>=1){ if(tid<s) s_red[tid]+=s_red[tid+s]; __syncthreads(); }
        float mean = s_red[0]/81.0f;
        __syncthreads();
        float kv = (tid<81)? (ridge-mean) : 0.f;
        s_red[tid] = fabsf(kv);
        __syncthreads();
        for(int s=128;s>0;s>>=1){ if(tid<s) s_red[tid]+=s_red[tid+s]; __syncthreads(); }
        float nrm = fmaxf(s_red[0], 1e-6f);
        if (tid<81) g_kern[i*81+tid] = kv/nrm + 0.05f*pd[i*81+tid];
    }
}

// =====================================================================
// k_conv3hp: tile 16x8. 3x3 conv 8->8 + gelu over halo region, carrier,
// cmean/hp/asup/densraw + per-tile stat partials. 256 blocks x 256 thr.
// =====================================================================
__global__ void k_conv3hp(const float* __restrict__ w, const float* __restrict__ bias){
    __shared__ float s_in[RCn*14*22];   // halo 3
    __shared__ float s_w[RCn*RCn*9];
    __shared__ float s_b[RCn];
    __shared__ float s_cm[12*20];
    __shared__ float s_dr[12*20];
    __shared__ float s_hp[10*18];
    __shared__ float s_red[256];
    int tid = threadIdx.x;              // 256
    int blk = blockIdx.x;               // 256 = 8 images * 32 tiles
    int b = blk >> 5;
    int t5 = blk & 31, ty = t5 >> 2, tx = t5 & 3;   // ty 0..7 (rows of 8), tx 0..3 (cols of 16)
    for(int idx=tid; idx<RCn*RCn*9; idx+=256) s_w[idx]=w[idx];
    if (tid < RCn) s_b[tid]=bias[tid];
    for(int idx=tid; idx<RCn*308; idx+=256){
        int ch = idx/308, rem = idx%308;
        int r = rem/22, c = rem%22;
        int gy = ty*8 + r - 3, gx = tx*16 + c - 3;
        float v = 0.f;
        if ((unsigned)gy<64u && (unsigned)gx<64u)
            v = g_c1[((b*RCn+ch)<<12) + (gy<<6) + gx];
        s_in[ch*308 + r*22 + c] = v;
    }
    __syncthreads();
    for(int i=tid; i<240; i+=256){
        int oy=i/20, ox=i%20;
        int gy=ty*8+oy-2, gx=tx*16+ox-2;
        float sum=0.f, asum=0.f;
        if((unsigned)gy<64u && (unsigned)gx<64u){
            float outv[RCn];
            #pragma unroll
            for(int o=0;o<RCn;o++){
                float acc = s_b[o];
                #pragma unroll
                for(int ic=0;ic<RCn;ic++){
                    const float* wr = &s_w[(o*RCn+ic)*9];
                    const float* ip = &s_in[ic*308 + oy*22 + ox];
                    #pragma unroll
                    for(int dy=0;dy<3;dy++)
                        #pragma unroll
                        for(int dx=0;dx<3;dx++)
                            acc = fmaf(wr[dy*3+dx], ip[dy*22+dx], acc);
                }
                float gv = geluf(acc);
                outv[o]=gv; sum+=gv; asum+=fabsf(gv);
            }
            if (oy>=2 && oy<10 && ox>=2 && ox<18){
                int pix = (gy<<6)+gx;
                #pragma unroll
                for(int o=0;o<RCn;o++) g_carrier[((b*RCn+o)<<12)+pix] = outv[o];
                g_densraw[(b<<12)+pix] = asum*0.125f;
            }
        }
        s_cm[i] = sum*0.125f;
        s_dr[i] = asum*0.125f;
    }
    __syncthreads();
    for(int i=tid;i<180;i+=256){
        int hy=i/18, hx=i%18;
        int gy=ty*8+hy-1, gx=tx*16+hx-1;
        float hp=0.f;
        if((unsigned)gy<64u && (unsigned)gx<64u){
            int r=hy+1, c=hx+1;
            float s=0.f;
            #pragma unroll
            for(int dy=-1;dy<=1;dy++)
                #pragma unroll
                for(int dx=-1;dx<=1;dx++)
                    s += s_cm[(r+dy)*20 + c+dx];
            hp = s_cm[r*20+c] - s/9.0f;
            if (hy>=1 && hy<9 && hx>=1 && hx<17)
                g_hp[(b<<12)+(gy<<6)+gx] = hp;
        }
        s_hp[i]=hp;
    }
    __syncthreads();
    bool act = tid < 128;
    int ly = (tid>>4) & 7, lx = tid&15;
    float a=0.f, d=0.f;
    if (act){
        float s=0.f;
        #pragma unroll
        for(int dy=0;dy<3;dy++)
            #pragma unroll
            for(int dx=0;dx<3;dx++)
                s += fabsf(s_hp[(ly+dy)*18 + lx+dx]);
        a = s/9.0f;
        int gi = (b<<12) + ((ty*8+ly)<<6) + tx*16+lx;
        g_asup[gi]=a;
        d = s_dr[(ly+2)*20 + lx+2];
    }
    s_red[tid]= act? a : 1e30f; __syncthreads();
    for(int s2=128;s2>0;s2>>=1){ if(tid<s2) s_red[tid]=fminf(s_red[tid],s_red[tid+s2]); __syncthreads(); }
    float mnA=s_red[0]; __syncthreads();
    s_red[tid]= act? a : -1e30f; __syncthreads();
    for(int s2=128;s2>0;s2>>=1){ if(tid<s2) s_red[tid]=fmaxf(s_red[tid],s_red[tid+s2]); __syncthreads(); }
    float mxA=s_red[0]; __syncthreads();
    s_red[tid]= act? d : 1e30f; __syncthreads();
    for(int s2=128;s2>0;s2>>=1){ if(tid<s2) s_red[tid]=fminf(s_red[tid],s_red[tid+s2]); __syncthreads(); }
    float mnD=s_red[0]; __syncthreads();
    s_red[tid]= act? d : -1e30f; __syncthreads();
    for(int s2=128;s2>0;s2>>=1){ if(tid<s2) s_red[tid]=fmaxf(s_red[tid],s_red[tid+s2]); __syncthreads(); }
    float mxD=s_red[0]; __syncthreads();
    s_red[tid]= act? d : 0.f; __syncthreads();
    for(int s2=128;s2>0;s2>>=1){ if(tid<s2) s_red[tid]+=s_red[tid+s2]; __syncthreads(); }
    if(tid==0){
        float* p = &g_part[(b*32 + t5)*5];
        p[0]=mnA; p[1]=mxA; p[2]=mnD; p[3]=mxD; p[4]=s_red[0];
    }
}

// =====================================================================
// k_rg: tile 16x8. 9x9 bank conv + softmax-top2 + gating + morphology
// + final ss + pm1+gelu -> g_h. 256 blocks x 256 threads.
// =====================================================================
__global__ void k_rg(const float* __restrict__ theta, const float* __restrict__ length,
                     const float* __restrict__ width, const float* __restrict__ plog,
                     const float* __restrict__ objn, const float* __restrict__ alpha,
                     const float* __restrict__ curv,
                     const float* __restrict__ pm1w, const float* __restrict__ pm1b){
    __shared__ float s_k[Pp*81];
    __shared__ float s_hp[18*26];
    __shared__ float s_mask[20*28];
    __shared__ float s_g0[20*28];
    __shared__ float s_er[16*24];
    __shared__ float s_ss[10*18];
    __shared__ float s_ob[10*18];
    __shared__ float s_st[5];
    __shared__ float s_p1[RCn*12];
    __shared__ float s_b1[RCn];
    int tid=threadIdx.x;                // 256
    int blk=blockIdx.x;                 // 256
    int b = blk>>5, t5 = blk&31, ty = t5>>2, tx = t5&3;
    for(int i=tid;i<Pp*81;i+=256) s_k[i]=g_kern[i];
    if(tid<RCn*12) s_p1[tid]=pm1w[tid];
    if(tid<RCn) s_b1[tid]=pm1b[tid];
    if(tid==0){
        float mnA=1e30f,mxA=-1e30f,mnD=1e30f,mxD=-1e30f,sD=0.f;
        for(int t=0;t<32;t++){
            const float* p=&g_part[(b*32+t)*5];
            mnA=fminf(mnA,p[0]); mxA=fmaxf(mxA,p[1]);
            mnD=fminf(mnD,p[2]); mxD=fmaxf(mxD,p[3]); sD+=p[4];
        }
        s_st[0]=mnA; s_st[1]=mxA; s_st[2]=mnD; s_st[3]=mxD; s_st[4]=sD/(float)HW;
    }
    for(int i=tid;i<468;i+=256){
        int r=i/26,c=i%26;
        int gy=ty*8+r-5, gx=tx*16+c-5;
        float v=0.f;
        if((unsigned)gy<64u && (unsigned)gx<64u) v=g_hp[(b<<12)+(gy<<6)+gx];
        s_hp[i]=v;
    }
    __syncthreads();
    float mnA=s_st[0],mxA=s_st[1],mnD=s_st[2],mxD=s_st[3],meanD=s_st[4];
    float mC = fmaxf(meanD,1e-6f);
    float dmn = mnD/mC, dmx = mxD/mC;
    float invA = 1.0f/fmaxf(mxA-mnA,1e-6f);
    float invD = 1.0f/fmaxf(dmx-dmn,1e-6f);
    for(int i=tid;i<560;i+=256){
        int r=i/28,c=i%28;
        int gy=ty*8+r-6, gx=tx*16+c-6;
        float mv=1.0f, g0=0.0f;
        if((unsigned)gy<64u && (unsigned)gx<64u){
            int gi=(b<<12)+(gy<<6)+gx;
            float csup = (g_asup[gi]-mnA)*invA;
            float dsup = (g_densraw[gi]/mC - dmn)*invD;
            float ev = 0.65f*csup + 0.35f*dsup;
            mv = (ev>=0.2f)?1.0f:0.0f;
            g0 = sigmf((ev-0.2f)*12.5f);
        }
        s_mask[i]=mv; s_g0[i]=g0;
    }
    const float COSO[8]={1.0f,0.70710678f,0.0f,-0.70710678f,-1.0f,-0.70710678f,0.0f,0.70710678f};
    const float SINO[8]={0.0f,0.70710678f,1.0f,0.70710678f,0.0f,-0.70710678f,-1.0f,-0.70710678f};
    const float LA[8]={0.45f,0.75f,1.05f,0.45f,0.75f,1.05f,0.45f,0.75f};
    const float WA[8]={0.14f,0.14f,0.14f,0.2f,0.2f,0.2f,0.28f,0.28f};
    __syncthreads();
    for(int i=tid;i<180;i+=256){
        int sy=i/18, sx=i%18;
        int gy=ty*8+sy-1, gx=tx*16+sx-1;
        float ssv=0.f, ov=0.f;
        if((unsigned)gy<64u && (unsigned)gx<64u){
            int gi=(b<<12)+(gy<<6)+gx;
            float resp[Pp];
            #pragma unroll
            for(int p=0;p<Pp;p++) resp[p]=0.f;
            #pragma unroll
            for(int dy=0;dy<9;dy++){
                #pragma unroll
                for(int dx=0;dx<9;dx++){
                    float hv = s_hp[(sy+dy)*26 + sx+dx];
                    int off = dy*9+dx;
                    #pragma unroll
                    for(int p=0;p<Pp;p++) resp[p]=fmaf(s_k[p*81+off],hv,resp[p]);
                }
            }
            float th = tanhf(theta[gi])*3.14159265358979f;
            float sth, cth; sincosf(th,&sth,&cth);
            float lv = sigmf(length[gi])*0.85f + 0.25f;
            float wv = sigmf(width[gi]) *0.22f + 0.08f;
            float bias[8];
            #pragma unroll
            for(int p=0;p<8;p++){
                float ts = cth*COSO[p] + sth*SINO[p];
                float dl = lv - LA[p];
                float dw = wv - WA[p];
                bias[p] = plog[((b*8+p)<<12) + (gy<<6)+gx] + 1.25f*ts - dl*dl*12.5f - dw*dw*100.0f;
            }
            int i1=0; float b1=bias[0];
            #pragma unroll
            for(int p=1;p<8;p++) if(bias[p]>b1){b1=bias[p];i1=p;}
            int i2=-1; float b2=-1e30f;
            #pragma unroll
            for(int p=0;p<8;p++){ if(p==i1) continue; if(bias[p]>b2){b2=bias[p];i2=p;} }
            float e = expf(b2-b1);
            float w1 = 1.0f/(1.0f+e);
            float w2 = e/(1.0f+e);
            #pragma unroll
            for(int p=0;p<8;p++){
                float wp = (p==i1)?w1:((p==i2)?w2:0.f);
                ssv = fmaf(wp, resp[p], ssv);
            }
            ov = sigmf(objn[gi]);
        }
        s_ss[i]=ssv; s_ob[i]=ov;
    }
    __syncthreads();
    for(int i=tid;i<384;i+=256){
        int ey=i/24, ex=i%24;
        int gy=ty*8+ey-4, gx=tx*16+ex-4;
        float m=0.f;
        if((unsigned)gy<64u && (unsigned)gx<64u){
            m=1.0f;
            #pragma unroll
            for(int dy=0;dy<5;dy++)
                #pragma unroll
                for(int dx=0;dx<5;dx++)
                    m=fminf(m, s_mask[(ey+dy)*28 + ex+dx]);
        }
        s_er[i]=m;
    }
    __syncthreads();
    if (tid < 128){
        int ly=(tid>>4)&7, lx=tid&15;
        float m9=0.f;
        #pragma unroll
        for(int dy=0;dy<9;dy++)
            #pragma unroll
            for(int dx=0;dx<9;dx++)
                m9=fmaxf(m9, s_er[(ly+dy)*24 + lx+dx]);
        float g5=0.f;
        #pragma unroll
        for(int dy=0;dy<5;dy++)
            #pragma unroll
            for(int dx=0;dx<5;dx++)
                g5=fmaxf(g5, s_g0[(ly+4+dy)*28 + lx+4+dx]);
        float gate = g5*m9;
        float so=0.f, sv=0.f;
        #pragma unroll
        for(int dy=0;dy<3;dy++)
            #pragma unroll
            for(int dx=0;dx<3;dx++){
                so += s_ob[(ly+dy)*18 + lx+dx];
                sv += s_ss[(ly+dy)*18 + lx+dx];
            }
        float blob = (so/9.0f)*gate;
        float ss2 = s_ss[(ly+1)*18 + lx+1] - sv/9.0f;
        int gi = (b<<12) + ((ty*8+ly)<<6) + tx*16+lx;
        float d = g_densraw[gi]/mC;
        float cv = tanhf(curv[gi]);
        float sg = sigmf(alpha[gi])*blob*(0.7f + 0.3f*fminf(fmaxf(d,0.f),2.0f));
        float ssf = sg*ss2*(1.0f + 0.15f*cv);
        float th2 = tanhf(theta[gi])*3.14159265358979f;
        float sth2, cth2; sincosf(th2,&sth2,&cth2);
        float f[12];
        #pragma unroll
        for(int o=0;o<RCn;o++) f[o] = g_carrier[((b*RCn+o)<<12) + (gi&4095)]*ssf;
        f[8]=ssf; f[9]=cth2*ssf; f[10]=sth2*ssf; f[11]=cv*ssf;
        #pragma unroll
        for(int o=0;o<RCn;o++){
            float acc = s_b1[o];
            #pragma unroll
            for(int j=0;j<12;j++) acc = fmaf(s_p1[o*12+j], f[j], acc);
            g_h[(o<<15) + gi] = geluf(acc);
        }
    }
}

// =====================================================================
// k_out: pure GEMV 8 -> 768, float4 pixels + float4 stores.
// 512 blocks (32 pixel-blocks x 16 channel splits of 48) x 256 threads.
// =====================================================================
__global__ void k_out(const float* __restrict__ pm2w, const float* __restrict__ pm2b,
                      float* __restrict__ out){
    __shared__ float s_w[48*RCn];
    __shared__ float s_b[48];
    int tid = threadIdx.x;            // 256
    int pb = blockIdx.x >> 4;         // pixel block 0..31
    int sp = blockIdx.x & 15;         // channel split 0..15 (48 out ch)
    for(int i=tid;i<48*RCn;i+=256) s_w[i]=pm2w[sp*48*RCn + i];
    if(tid<48) s_b[tid]=pm2b[sp*48 + tid];
    __syncthreads();
    int g4 = pb*256 + tid;            // float4 pixel group, 0..8191
    int b = g4 >> 10;
    int pix = (g4 << 2) & 4095;
    float4 h4[RCn];
    #pragma unroll
    for(int k=0;k<RCn;k++) h4[k] = __ldg((const float4*)&g_h[(k<<15) + (g4<<2)]);
    float* op = out + ((size_t)b*FCn + sp*48)*HW + pix;
    #pragma unroll 4
    for(int o=0;o<48;o++){
        const float* wr = &s_w[o*RCn];
        float bo = s_b[o];
        float4 a; a.x=bo; a.y=bo; a.z=bo; a.w=bo;
        #pragma unroll
        for(int k=0;k<RCn;k++){
            float wv = wr[k];
            a.x = fmaf(wv, h4[k].x, a.x);
            a.y = fmaf(wv, h4[k].y, a.y);
            a.z = fmaf(wv, h4[k].z, a.z);
            a.w = fmaf(wv, h4[k].w, a.w);
        }
        *(float4*)(op + (size_t)o*HW) = a;
    }
}

extern "C" void kernel_launch(void* const* d_in, const int* in_sizes, int n_in,
                              void* d_out, int out_size){
    const float* fm     = (const float*)d_in[0];
    const float* theta  = (const float*)d_in[1];
    const float* length = (const float*)d_in[2];
    const float* width  = (const float*)d_in[3];
    const float* curv   = (const float*)d_in[4];
    const float* alpha  = (const float*)d_in[5];
    const float* objn   = (const float*)d_in[6];
    const float* plog   = (const float*)d_in[7];
    const float* fp1w   = (const float*)d_in[8];
    const float* fp1b   = (const float*)d_in[9];
    const float* fp2w   = (const float*)d_in[10];
    const float* fp2b   = (const float*)d_in[11];
    const float* pm1w   = (const float*)d_in[12];
    const float* pm1b   = (const float*)d_in[13];
    const float* pm2w   = (const float*)d_in[14];
    const float* pm2b   = (const float*)d_in[15];
    const float* pd     = (const float*)d_in[16];
    float* out = (float*)d_out;

    k_conv1  <<<512, 256>>>(fm, fp1w, fp1b, pd);
    k_conv3hp<<<256, 256>>>(fp2w, fp2b);
    k_rg     <<<256, 256>>>(theta, length, width, plog, objn, alpha, curv, pm1w, pm1b);
    k_out    <<<512, 256>>>(pm2w, pm2b, out);
}